// round 2
// baseline (speedup 1.0000x reference)
#include <cuda_runtime.h>

// ---------------------------------------------------------------------------
// Problem constants
//   x:  [512, 512]   z: [512, 256]
//   Wq: [256, 32768] Wk/Wv: [512, 32768]  Wo: [32768, 512]
//   D = 32768 = 8 heads * 64 seq * 64 d_tensor
// ---------------------------------------------------------------------------
#define TOK   512
#define DTOT  32768

// Scratch (device globals — no allocations allowed in kernel_launch)
__device__ float g_Q [TOK * (size_t)DTOT];
__device__ float g_K [TOK * (size_t)DTOT];
__device__ float g_V [TOK * (size_t)DTOT];
__device__ float g_AO[TOK * (size_t)DTOT];

// ---------------------------------------------------------------------------
// SGEMM: C[M,N] = A[M,K] @ B[K,N] + bias[N]
// 128x128 block tile, BK=16, 256 threads, 8x8 per-thread micro-tile.
// ---------------------------------------------------------------------------
__global__ __launch_bounds__(256, 2)
void sgemm_bias_kernel(const float* __restrict__ A, const float* __restrict__ B,
                       const float* __restrict__ bias, float* __restrict__ C,
                       int M, int N, int K)
{
    // Row stride MUST be a multiple of 4 floats (16 B) for float4 reads.
    __shared__ __align__(16) float As[16][132];   // A transposed: As[k][m]
    __shared__ __align__(16) float Bs[16][128];

    const int tid = threadIdx.x;
    const int m0  = blockIdx.y << 7;
    const int n0  = blockIdx.x << 7;
    const int ty  = tid >> 4;   // 0..15
    const int tx  = tid & 15;   // 0..15

    // A tile loads: 512 float4 (128 rows x 4 chunks), 2 per thread
    const int arow0 = tid >> 2;
    const int arow1 = (tid + 256) >> 2;
    const int akc   = (tid & 3) << 2;
    // B tile loads: 512 float4 (16 rows x 32 chunks), 2 per thread
    const int brow0 = tid >> 5;
    const int brow1 = (tid + 256) >> 5;
    const int bc    = (tid & 31) << 2;

    const float* Ap0 = A + (size_t)(m0 + arow0) * K + akc;
    const float* Ap1 = A + (size_t)(m0 + arow1) * K + akc;
    const float* Bp0 = B + (size_t)brow0 * N + n0 + bc;
    const float* Bp1 = B + (size_t)brow1 * N + n0 + bc;

    float acc[8][8];
#pragma unroll
    for (int i = 0; i < 8; i++)
#pragma unroll
        for (int j = 0; j < 8; j++) acc[i][j] = 0.f;

    float4 pa0 = *(const float4*)(Ap0);
    float4 pa1 = *(const float4*)(Ap1);
    float4 pb0 = *(const float4*)(Bp0);
    float4 pb1 = *(const float4*)(Bp1);

    const int KT = K >> 4;
    for (int kt = 0; kt < KT; kt++) {
        As[akc + 0][arow0] = pa0.x;  As[akc + 1][arow0] = pa0.y;
        As[akc + 2][arow0] = pa0.z;  As[akc + 3][arow0] = pa0.w;
        As[akc + 0][arow1] = pa1.x;  As[akc + 1][arow1] = pa1.y;
        As[akc + 2][arow1] = pa1.z;  As[akc + 3][arow1] = pa1.w;
        *(float4*)&Bs[brow0][bc] = pb0;
        *(float4*)&Bs[brow1][bc] = pb1;
        __syncthreads();

        if (kt + 1 < KT) {
            pa0 = *(const float4*)(Ap0 + (kt + 1) * 16);
            pa1 = *(const float4*)(Ap1 + (kt + 1) * 16);
            pb0 = *(const float4*)(Bp0 + (size_t)(kt + 1) * 16 * N);
            pb1 = *(const float4*)(Bp1 + (size_t)(kt + 1) * 16 * N);
        }

#pragma unroll
        for (int k = 0; k < 16; k++) {
            float ra[8], rb[8];
            *(float4*)(ra)     = *(const float4*)&As[k][ty * 8];
            *(float4*)(ra + 4) = *(const float4*)&As[k][ty * 8 + 4];
            *(float4*)(rb)     = *(const float4*)&Bs[k][tx * 8];
            *(float4*)(rb + 4) = *(const float4*)&Bs[k][tx * 8 + 4];
#pragma unroll
            for (int i = 0; i < 8; i++)
#pragma unroll
                for (int j = 0; j < 8; j++)
                    acc[i][j] += ra[i] * rb[j];
        }
        __syncthreads();
    }

    float bs[8];
    *(float4*)(bs)     = *(const float4*)(bias + n0 + tx * 8);
    *(float4*)(bs + 4) = *(const float4*)(bias + n0 + tx * 8 + 4);
#pragma unroll
    for (int i = 0; i < 8; i++) {
        float4 v0, v1;
        v0.x = acc[i][0] + bs[0]; v0.y = acc[i][1] + bs[1];
        v0.z = acc[i][2] + bs[2]; v0.w = acc[i][3] + bs[3];
        v1.x = acc[i][4] + bs[4]; v1.y = acc[i][5] + bs[5];
        v1.z = acc[i][6] + bs[6]; v1.w = acc[i][7] + bs[7];
        float* cp = C + (size_t)(m0 + ty * 8 + i) * N + n0 + tx * 8;
        *(float4*)(cp)     = v0;
        *(float4*)(cp + 4) = v1;
    }
}

// ---------------------------------------------------------------------------
// Split-K SGEMM for the output projection (K = 32768, M = N = 512).
// Each block handles a 128x128 tile over a 1024-deep K chunk, atomicAdd out.
// ---------------------------------------------------------------------------
__global__ __launch_bounds__(256, 2)
void sgemm_splitk_kernel(const float* __restrict__ A, const float* __restrict__ B,
                         float* __restrict__ C, int M, int N, int K, int kchunk)
{
    __shared__ __align__(16) float As[16][132];
    __shared__ __align__(16) float Bs[16][128];

    const int tid  = threadIdx.x;
    const int m0   = blockIdx.y << 7;
    const int n0   = blockIdx.x << 7;
    const int kbeg = blockIdx.z * kchunk;
    const int ty   = tid >> 4;
    const int tx   = tid & 15;

    const int arow0 = tid >> 2;
    const int arow1 = (tid + 256) >> 2;
    const int akc   = (tid & 3) << 2;
    const int brow0 = tid >> 5;
    const int brow1 = (tid + 256) >> 5;
    const int bc    = (tid & 31) << 2;

    const float* Ap0 = A + (size_t)(m0 + arow0) * K + kbeg + akc;
    const float* Ap1 = A + (size_t)(m0 + arow1) * K + kbeg + akc;
    const float* Bp0 = B + (size_t)(kbeg + brow0) * N + n0 + bc;
    const float* Bp1 = B + (size_t)(kbeg + brow1) * N + n0 + bc;

    float acc[8][8];
#pragma unroll
    for (int i = 0; i < 8; i++)
#pragma unroll
        for (int j = 0; j < 8; j++) acc[i][j] = 0.f;

    float4 pa0 = *(const float4*)(Ap0);
    float4 pa1 = *(const float4*)(Ap1);
    float4 pb0 = *(const float4*)(Bp0);
    float4 pb1 = *(const float4*)(Bp1);

    const int KT = kchunk >> 4;
    for (int kt = 0; kt < KT; kt++) {
        As[akc + 0][arow0] = pa0.x;  As[akc + 1][arow0] = pa0.y;
        As[akc + 2][arow0] = pa0.z;  As[akc + 3][arow0] = pa0.w;
        As[akc + 0][arow1] = pa1.x;  As[akc + 1][arow1] = pa1.y;
        As[akc + 2][arow1] = pa1.z;  As[akc + 3][arow1] = pa1.w;
        *(float4*)&Bs[brow0][bc] = pb0;
        *(float4*)&Bs[brow1][bc] = pb1;
        __syncthreads();

        if (kt + 1 < KT) {
            pa0 = *(const float4*)(Ap0 + (kt + 1) * 16);
            pa1 = *(const float4*)(Ap1 + (kt + 1) * 16);
            pb0 = *(const float4*)(Bp0 + (size_t)(kt + 1) * 16 * N);
            pb1 = *(const float4*)(Bp1 + (size_t)(kt + 1) * 16 * N);
        }

#pragma unroll
        for (int k = 0; k < 16; k++) {
            float ra[8], rb[8];
            *(float4*)(ra)     = *(const float4*)&As[k][ty * 8];
            *(float4*)(ra + 4) = *(const float4*)&As[k][ty * 8 + 4];
            *(float4*)(rb)     = *(const float4*)&Bs[k][tx * 8];
            *(float4*)(rb + 4) = *(const float4*)&Bs[k][tx * 8 + 4];
#pragma unroll
            for (int i = 0; i < 8; i++)
#pragma unroll
                for (int j = 0; j < 8; j++)
                    acc[i][j] += ra[i] * rb[j];
        }
        __syncthreads();
    }

#pragma unroll
    for (int i = 0; i < 8; i++) {
        float* cp = C + (size_t)(m0 + ty * 8 + i) * N + n0 + tx * 8;
#pragma unroll
        for (int j = 0; j < 8; j++)
            atomicAdd(cp + j, acc[i][j]);
    }
}

// ---------------------------------------------------------------------------
// Fused attention: per block, one (bn, head) pair and a 32-row q slice.
// Q[32,64] @ K[64,64]^T -> softmax -> @ V[64,64]
// grid = 8192 (4096 bnh pairs * 2 q-slices), 256 threads.
// ---------------------------------------------------------------------------
__global__ __launch_bounds__(256, 4)
void attn_kernel(const float* __restrict__ Qg, const float* __restrict__ Kg,
                 const float* __restrict__ Vg, float* __restrict__ Og)
{
    __shared__ __align__(16) float Qs[32][68];
    __shared__ __align__(16) float KVs[64][68];
    __shared__ __align__(16) float Sc[32][65];

    const int bx  = blockIdx.x;
    const int qb  = bx & 1;       // q slice: 0 -> rows 0..31, 1 -> rows 32..63
    const int bnh = bx >> 1;      // 0..4095  (bn*8 + h), head stride = 4096
    const size_t base = (size_t)bnh * 4096;

    const float* Qp = Qg + base + qb * 2048;
    const float* Kp = Kg + base;
    const float* Vp = Vg + base;
    float*       Op = Og + base + qb * 2048;

    const int tid = threadIdx.x;

    // Load Q (32x64) and K (64x64)
    for (int f = tid; f < 512; f += 256) {
        int r = f >> 4, c = (f & 15) << 2;
        *(float4*)&Qs[r][c] = *(const float4*)(Qp + r * 64 + c);
    }
    for (int f = tid; f < 1024; f += 256) {
        int r = f >> 4, c = (f & 15) << 2;
        *(float4*)&KVs[r][c] = *(const float4*)(Kp + r * 64 + c);
    }
    __syncthreads();

    const int q2 = tid >> 4;   // 0..15 : q rows {2*q2, 2*q2+1}
    const int kg = tid & 15;   // 0..15 : k cols {kg, 16+kg, 32+kg, 48+kg}

    float s[2][4] = {{0.f,0.f,0.f,0.f},{0.f,0.f,0.f,0.f}};
#pragma unroll
    for (int d4 = 0; d4 < 16; d4++) {
        float4 q0 = *(const float4*)&Qs[q2 * 2 + 0][d4 * 4];
        float4 q1 = *(const float4*)&Qs[q2 * 2 + 1][d4 * 4];
#pragma unroll
        for (int j = 0; j < 4; j++) {
            float4 kv = *(const float4*)&KVs[j * 16 + kg][d4 * 4];
            s[0][j] += q0.x * kv.x + q0.y * kv.y + q0.z * kv.z + q0.w * kv.w;
            s[1][j] += q1.x * kv.x + q1.y * kv.y + q1.z * kv.z + q1.w * kv.w;
        }
    }

    // softmax across k (16 threads per row, shfl over kg bits 0..3)
#pragma unroll
    for (int qq = 0; qq < 2; qq++) {
        float mx = -1e30f;
#pragma unroll
        for (int j = 0; j < 4; j++) {
            s[qq][j] *= 0.125f;          // 1/sqrt(64)
            mx = fmaxf(mx, s[qq][j]);
        }
#pragma unroll
        for (int m = 8; m >= 1; m >>= 1)
            mx = fmaxf(mx, __shfl_xor_sync(0xffffffffu, mx, m));
        float sum = 0.f;
#pragma unroll
        for (int j = 0; j < 4; j++) {
            s[qq][j] = __expf(s[qq][j] - mx);
            sum += s[qq][j];
        }
#pragma unroll
        for (int m = 8; m >= 1; m >>= 1)
            sum += __shfl_xor_sync(0xffffffffu, sum, m);
        float inv = 1.f / sum;
#pragma unroll
        for (int j = 0; j < 4; j++)
            Sc[q2 * 2 + qq][j * 16 + kg] = s[qq][j] * inv;
    }
    __syncthreads();

    // Load V over K
    for (int f = tid; f < 1024; f += 256) {
        int r = f >> 4, c = (f & 15) << 2;
        *(float4*)&KVs[r][c] = *(const float4*)(Vp + r * 64 + c);
    }
    __syncthreads();

    // AV: thread (q2, dg=kg) -> rows {2q2, 2q2+1}, cols dg*4..dg*4+3
    float4 o0 = {0.f,0.f,0.f,0.f}, o1 = {0.f,0.f,0.f,0.f};
#pragma unroll
    for (int k = 0; k < 64; k++) {
        float4 vv = *(const float4*)&KVs[k][kg * 4];
        float a0 = Sc[q2 * 2 + 0][k];
        float a1 = Sc[q2 * 2 + 1][k];
        o0.x += a0 * vv.x; o0.y += a0 * vv.y; o0.z += a0 * vv.z; o0.w += a0 * vv.w;
        o1.x += a1 * vv.x; o1.y += a1 * vv.y; o1.z += a1 * vv.z; o1.w += a1 * vv.w;
    }
    *(float4*)(Op + (q2 * 2 + 0) * 64 + kg * 4) = o0;
    *(float4*)(Op + (q2 * 2 + 1) * 64 + kg * 4) = o1;
}

// ---------------------------------------------------------------------------
// out[m, n] = bo[n]  (bias init before split-K accumulation)
// ---------------------------------------------------------------------------
__global__ void init_out_kernel(float* __restrict__ out, const float* __restrict__ bo)
{
    int i = blockIdx.x * 256 + threadIdx.x;   // 262144 elements
    out[i] = bo[i & 511];
}

// ---------------------------------------------------------------------------
extern "C" void kernel_launch(void* const* d_in, const int* in_sizes, int n_in,
                              void* d_out, int out_size)
{
    const float* x  = (const float*)d_in[0];
    const float* z  = (const float*)d_in[1];
    const float* Wq = (const float*)d_in[2];
    const float* bq = (const float*)d_in[3];
    const float* Wk = (const float*)d_in[4];
    const float* bk = (const float*)d_in[5];
    const float* Wv = (const float*)d_in[6];
    const float* bv = (const float*)d_in[7];
    const float* Wo = (const float*)d_in[8];
    const float* bo = (const float*)d_in[9];
    float* out = (float*)d_out;

    float *Qd, *Kd, *Vd, *AOd;
    cudaGetSymbolAddress((void**)&Qd,  g_Q);
    cudaGetSymbolAddress((void**)&Kd,  g_K);
    cudaGetSymbolAddress((void**)&Vd,  g_V);
    cudaGetSymbolAddress((void**)&AOd, g_AO);

    dim3 gQKV(DTOT / 128, TOK / 128);   // (256, 4)
    sgemm_bias_kernel<<<gQKV, 256>>>(z, Wq, bq, Qd, TOK, DTOT, 256);
    sgemm_bias_kernel<<<gQKV, 256>>>(x, Wk, bk, Kd, TOK, DTOT, 512);
    sgemm_bias_kernel<<<gQKV, 256>>>(x, Wv, bv, Vd, TOK, DTOT, 512);

    attn_kernel<<<8192, 256>>>(Qd, Kd, Vd, AOd);

    init_out_kernel<<<1024, 256>>>(out, bo);

    dim3 gO(4, 4, 32);                   // 128x128 tiles, 32-way split-K (chunk 1024)
    sgemm_splitk_kernel<<<gO, 256>>>(AOd, Wo, out, 512, 512, DTOT, 1024);
}

// round 4
// speedup vs baseline: 1.6482x; 1.6482x over previous
#include <cuda_runtime.h>
#include <cuda_bf16.h>
#include <cstdint>

// ---------------------------------------------------------------------------
//   x: [512,512]  z: [512,256]
//   Wq: [256,32768]  Wk/Wv: [512,32768]  Wo: [32768,512]
//   D = 32768 = 8 heads * 64 seq * 64 d_tensor
// ---------------------------------------------------------------------------
#define TOK   512
#define DTOT  32768
#define NSPLIT 32

__device__ float g_Q [TOK * (size_t)DTOT];   // Q; reused as split-K partials
__device__ float g_K [TOK * (size_t)DTOT];
__device__ float g_V [TOK * (size_t)DTOT];
__device__ float g_AO[TOK * (size_t)DTOT];

// ---------------------------------------------------------------------------
// helpers (family-portable ISA only: ldmatrix + mma.sync, no tcgen05)
// ---------------------------------------------------------------------------
__device__ __forceinline__ uint32_t smem_u32(const void* p) {
    uint32_t a;
    asm("{ .reg .u64 t; cvta.to.shared.u64 t, %1; cvt.u32.u64 %0, t; }" : "=r"(a) : "l"(p));
    return a;
}

__device__ __forceinline__ void ldm4(uint32_t r[4], uint32_t addr) {
    asm volatile("ldmatrix.sync.aligned.m8n8.x4.shared.b16 {%0,%1,%2,%3}, [%4];"
                 : "=r"(r[0]), "=r"(r[1]), "=r"(r[2]), "=r"(r[3]) : "r"(addr));
}
__device__ __forceinline__ void ldm4t(uint32_t r[4], uint32_t addr) {
    asm volatile("ldmatrix.sync.aligned.m8n8.x4.trans.shared.b16 {%0,%1,%2,%3}, [%4];"
                 : "=r"(r[0]), "=r"(r[1]), "=r"(r[2]), "=r"(r[3]) : "r"(addr));
}
__device__ __forceinline__ void mma16816(float c[4], const uint32_t a[4], const uint32_t b[2]) {
    asm volatile(
        "mma.sync.aligned.m16n8k16.row.col.f32.bf16.bf16.f32 "
        "{%0,%1,%2,%3}, {%4,%5,%6,%7}, {%8,%9}, {%0,%1,%2,%3};"
        : "+f"(c[0]), "+f"(c[1]), "+f"(c[2]), "+f"(c[3])
        : "r"(a[0]), "r"(a[1]), "r"(a[2]), "r"(a[3]), "r"(b[0]), "r"(b[1]));
}
// pack two floats as bf16x2 (lo = e0, hi = e1)
__device__ __forceinline__ uint32_t pack2(float e0, float e1) {
    uint32_t r;
    asm("cvt.rn.bf16x2.f32 %0, %1, %2;" : "=r"(r) : "f"(e1), "f"(e0));
    return r;
}

union Pack8 { unsigned long long u64; __nv_bfloat16 h[4]; };
__device__ __forceinline__ void split2(float v, __nv_bfloat16& h, __nv_bfloat16& l) {
    h = __float2bfloat16(v);
    l = __float2bfloat16(v - __bfloat162float(h));
}

// ---------------------------------------------------------------------------
// GEMM C[M,N] = A[M,K] @ B[K,N] (+bias) via mma.sync bf16 split-precision.
// 512 threads, block tile 128x128, BK=32; warp tile 32x32 (warp grid 4x4).
// grid: (N/128, M/128, splits); C += z*csplit; ksize = K per split.
// ---------------------------------------------------------------------------
#define LDA_S 40    // bf16 elems per A smem row (32 + 8 pad)
#define LDB_S 136   // bf16 elems per B smem row (128 + 8 pad)

__global__ __launch_bounds__(512)
void gemm_mma_kernel(const float* __restrict__ A, int lda,
                     const float* __restrict__ B, int ldb,
                     const float* __restrict__ bias,
                     float* __restrict__ C, int ldc,
                     size_t csplit, int ksize)
{
    __shared__ __align__(16) __nv_bfloat16 Ah[128 * LDA_S];
    __shared__ __align__(16) __nv_bfloat16 Al[128 * LDA_S];
    __shared__ __align__(16) __nv_bfloat16 Bh[32 * LDB_S];
    __shared__ __align__(16) __nv_bfloat16 Bl[32 * LDB_S];

    const int tid = threadIdx.x, lane = tid & 31, wid = tid >> 5;
    const int wm = wid & 3, wn = wid >> 2;
    const int n0 = blockIdx.x << 7, m0 = blockIdx.y << 7;
    const int kbeg = blockIdx.z * ksize;
    C += (size_t)blockIdx.z * csplit;

    float acc[2][4][4];
#pragma unroll
    for (int i = 0; i < 2; i++)
#pragma unroll
        for (int j = 0; j < 4; j++)
#pragma unroll
            for (int k = 0; k < 4; k++) acc[i][j][k] = 0.f;

    const int lr = lane & 15, lc = lane >> 4;
    const uint32_t ahb = smem_u32(Ah), alb = smem_u32(Al);
    const uint32_t bhb = smem_u32(Bh), blb = smem_u32(Bl);

    const int arow = tid >> 3, ac4 = (tid & 7) << 2;   // 64 rows/pass, 2 passes
    const int brow = tid >> 5, bc4 = (tid & 31) << 2;  // 16 rows/pass, 2 passes

    const int nch = ksize >> 5;
    for (int ch = 0; ch < nch; ch++) {
        const int kc = kbeg + (ch << 5);
        __syncthreads();
#pragma unroll
        for (int i = 0; i < 2; i++) {
            int r = arow + (i << 6);
            float4 v = *(const float4*)(A + (size_t)(m0 + r) * lda + kc + ac4);
            Pack8 ph, pl;
            split2(v.x, ph.h[0], pl.h[0]);
            split2(v.y, ph.h[1], pl.h[1]);
            split2(v.z, ph.h[2], pl.h[2]);
            split2(v.w, ph.h[3], pl.h[3]);
            *(unsigned long long*)((char*)Ah + 2 * (r * LDA_S + ac4)) = ph.u64;
            *(unsigned long long*)((char*)Al + 2 * (r * LDA_S + ac4)) = pl.u64;
        }
#pragma unroll
        for (int i = 0; i < 2; i++) {
            int r = brow + (i << 4);
            float4 v = *(const float4*)(B + (size_t)(kc + r) * ldb + n0 + bc4);
            Pack8 ph, pl;
            split2(v.x, ph.h[0], pl.h[0]);
            split2(v.y, ph.h[1], pl.h[1]);
            split2(v.z, ph.h[2], pl.h[2]);
            split2(v.w, ph.h[3], pl.h[3]);
            *(unsigned long long*)((char*)Bh + 2 * (r * LDB_S + bc4)) = ph.u64;
            *(unsigned long long*)((char*)Bl + 2 * (r * LDB_S + bc4)) = pl.u64;
        }
        __syncthreads();

#pragma unroll
        for (int ks = 0; ks < 2; ks++) {
            uint32_t a_h[2][4], a_l[2][4];
#pragma unroll
            for (int mf = 0; mf < 2; mf++) {
                uint32_t adr = 2 * ((wm * 32 + mf * 16 + lr) * LDA_S + ks * 16 + lc * 8);
                ldm4(a_h[mf], ahb + adr);
                ldm4(a_l[mf], alb + adr);
            }
            uint32_t b_h[2][4], b_l[2][4];
#pragma unroll
            for (int nb = 0; nb < 2; nb++) {
                uint32_t adr = 2 * ((ks * 16 + lr) * LDB_S + wn * 32 + nb * 16 + lc * 8);
                ldm4t(b_h[nb], bhb + adr);
                ldm4t(b_l[nb], blb + adr);
            }
#pragma unroll
            for (int mf = 0; mf < 2; mf++)
#pragma unroll
                for (int nb = 0; nb < 2; nb++)
#pragma unroll
                    for (int hf = 0; hf < 2; hf++) {
                        float* c = acc[mf][nb * 2 + hf];
                        uint32_t bhh[2] = {b_h[nb][hf * 2], b_h[nb][hf * 2 + 1]};
                        uint32_t bll[2] = {b_l[nb][hf * 2], b_l[nb][hf * 2 + 1]};
                        mma16816(c, a_h[mf], bhh);
                        mma16816(c, a_h[mf], bll);
                        mma16816(c, a_l[mf], bhh);
                    }
        }
    }

    const int rbase = m0 + wm * 32 + (lane >> 2);
    const int cb = n0 + wn * 32 + (lane & 3) * 2;
#pragma unroll
    for (int mf = 0; mf < 2; mf++)
#pragma unroll
        for (int nf = 0; nf < 4; nf++) {
            int rr = rbase + mf * 16;
            int cc = cb + nf * 8;
            float2 v0 = make_float2(acc[mf][nf][0], acc[mf][nf][1]);
            float2 v1 = make_float2(acc[mf][nf][2], acc[mf][nf][3]);
            if (bias) {
                float2 bb = *(const float2*)(bias + cc);
                v0.x += bb.x; v0.y += bb.y;
                v1.x += bb.x; v1.y += bb.y;
            }
            *(float2*)(C + (size_t)rr * ldc + cc) = v0;
            *(float2*)(C + (size_t)(rr + 8) * ldc + cc) = v1;
        }
}

// ---------------------------------------------------------------------------
// Tensor-core attention: one head per 128-thread block (4 warps, 16 q-rows
// each). S = Q@K^T (split bf16), in-register softmax, O = P@V (split bf16).
// ---------------------------------------------------------------------------
#define ALD 72   // bf16 elems per smem row (64 + 8 pad)

__global__ __launch_bounds__(128)
void attn_mma_kernel(const float* __restrict__ Qg, const float* __restrict__ Kg,
                     const float* __restrict__ Vg, float* __restrict__ Og)
{
    extern __shared__ __align__(16) char smr[];
    __nv_bfloat16* sp = (__nv_bfloat16*)smr;
    __nv_bfloat16 *QH = sp,          *QL = sp + 4608,
                  *KH = sp + 9216,   *KL = sp + 13824,
                  *VH = sp + 18432,  *VL = sp + 23040;

    const int tid = threadIdx.x, lane = tid & 31, w = tid >> 5;
    const size_t base = (size_t)blockIdx.x * 4096;

    // load + split Q, K, V (each 64x64 fp32)
    {
        const float* srcs[3] = {Qg + base, Kg + base, Vg + base};
        __nv_bfloat16* dh[3] = {QH, KH, VH};
        __nv_bfloat16* dl[3] = {QL, KL, VL};
#pragma unroll
        for (int t = 0; t < 3; t++) {
            for (int f = tid; f < 1024; f += 128) {
                int r = f >> 4, c = (f & 15) << 2;
                float4 v = *(const float4*)(srcs[t] + r * 64 + c);
                Pack8 ph, pl;
                split2(v.x, ph.h[0], pl.h[0]);
                split2(v.y, ph.h[1], pl.h[1]);
                split2(v.z, ph.h[2], pl.h[2]);
                split2(v.w, ph.h[3], pl.h[3]);
                *(unsigned long long*)((char*)dh[t] + 2 * (r * ALD + c)) = ph.u64;
                *(unsigned long long*)((char*)dl[t] + 2 * (r * ALD + c)) = pl.u64;
            }
        }
    }
    __syncthreads();

    const int lr = lane & 15, lc = lane >> 4;
    const uint32_t qh = smem_u32(QH), ql = smem_u32(QL);
    const uint32_t kh = smem_u32(KH), kl = smem_u32(KL);
    const uint32_t vh = smem_u32(VH), vl = smem_u32(VL);

    // ---- S = Q @ K^T : warp w owns q rows 16w..16w+15, full 64 k-cols
    float S[8][4];
#pragma unroll
    for (int i = 0; i < 8; i++)
#pragma unroll
        for (int j = 0; j < 4; j++) S[i][j] = 0.f;

#pragma unroll
    for (int ks = 0; ks < 4; ks++) {
        uint32_t a_h[4], a_l[4];
        uint32_t adr = 2 * ((w * 16 + lr) * ALD + ks * 16 + lc * 8);
        ldm4(a_h, qh + adr);
        ldm4(a_l, ql + adr);
#pragma unroll
        for (int nb = 0; nb < 4; nb++) {
            // K is [seq][d] = k-major B: non-trans ldmatrix, addresses over seq
            uint32_t badr = 2 * ((nb * 16 + (lane & 7) + (lane >> 4) * 8) * ALD
                                 + ks * 16 + ((lane >> 3) & 1) * 8);
            uint32_t b_h[4], b_l[4];
            ldm4(b_h, kh + badr);
            ldm4(b_l, kl + badr);
#pragma unroll
            for (int hf = 0; hf < 2; hf++) {
                float* c = S[nb * 2 + hf];
                uint32_t bhh[2] = {b_h[hf * 2], b_h[hf * 2 + 1]};
                uint32_t bll[2] = {b_l[hf * 2], b_l[hf * 2 + 1]};
                mma16816(c, a_h, bhh);
                mma16816(c, a_h, bll);
                mma16816(c, a_l, bhh);
            }
        }
    }

    // ---- softmax in fragments: rows lane>>2 (c0,c1) and lane>>2+8 (c2,c3)
    float mlo = -1e30f, mhi = -1e30f;
#pragma unroll
    for (int nf = 0; nf < 8; nf++) {
        S[nf][0] *= 0.125f; S[nf][1] *= 0.125f;
        S[nf][2] *= 0.125f; S[nf][3] *= 0.125f;
        mlo = fmaxf(mlo, fmaxf(S[nf][0], S[nf][1]));
        mhi = fmaxf(mhi, fmaxf(S[nf][2], S[nf][3]));
    }
    mlo = fmaxf(mlo, __shfl_xor_sync(0xffffffffu, mlo, 1));
    mlo = fmaxf(mlo, __shfl_xor_sync(0xffffffffu, mlo, 2));
    mhi = fmaxf(mhi, __shfl_xor_sync(0xffffffffu, mhi, 1));
    mhi = fmaxf(mhi, __shfl_xor_sync(0xffffffffu, mhi, 2));

    float slo = 0.f, shi = 0.f;
#pragma unroll
    for (int nf = 0; nf < 8; nf++) {
        S[nf][0] = __expf(S[nf][0] - mlo); slo += S[nf][0];
        S[nf][1] = __expf(S[nf][1] - mlo); slo += S[nf][1];
        S[nf][2] = __expf(S[nf][2] - mhi); shi += S[nf][2];
        S[nf][3] = __expf(S[nf][3] - mhi); shi += S[nf][3];
    }
    slo += __shfl_xor_sync(0xffffffffu, slo, 1);
    slo += __shfl_xor_sync(0xffffffffu, slo, 2);
    shi += __shfl_xor_sync(0xffffffffu, shi, 1);
    shi += __shfl_xor_sync(0xffffffffu, shi, 2);
    const float ilo = 1.f / slo, ihi = 1.f / shi;
#pragma unroll
    for (int nf = 0; nf < 8; nf++) {
        S[nf][0] *= ilo; S[nf][1] *= ilo;
        S[nf][2] *= ihi; S[nf][3] *= ihi;
    }

    // ---- P fragments: reuse c-frag layout as a-frags (hi/lo split in regs)
    uint32_t p_h[4][4], p_l[4][4];
#pragma unroll
    for (int j = 0; j < 4; j++) {
        const float* e[4] = {S[2 * j], 0, S[2 * j + 1], 0};
#pragma unroll
        for (int q = 0; q < 2; q++) {         // q=0: n-block 2j, q=1: 2j+1
            const float* s = (q == 0) ? S[2 * j] : S[2 * j + 1];
            float h0 = __bfloat162float(__float2bfloat16(s[0]));
            float h1 = __bfloat162float(__float2bfloat16(s[1]));
            float h2 = __bfloat162float(__float2bfloat16(s[2]));
            float h3 = __bfloat162float(__float2bfloat16(s[3]));
            p_h[j][q * 2 + 0] = pack2(s[0], s[1]);
            p_h[j][q * 2 + 1] = pack2(s[2], s[3]);
            p_l[j][q * 2 + 0] = pack2(s[0] - h0, s[1] - h1);
            p_l[j][q * 2 + 1] = pack2(s[2] - h2, s[3] - h3);
        }
        (void)e;
    }

    // ---- O = P @ V
    float O[8][4];
#pragma unroll
    for (int i = 0; i < 8; i++)
#pragma unroll
        for (int j = 0; j < 4; j++) O[i][j] = 0.f;

#pragma unroll
    for (int j = 0; j < 4; j++) {
#pragma unroll
        for (int nb = 0; nb < 4; nb++) {
            // V is [seq][d]: trans ldmatrix, addresses over seq (k)
            uint32_t badr = 2 * ((j * 16 + lr) * ALD + nb * 16 + lc * 8);
            uint32_t b_h[4], b_l[4];
            ldm4t(b_h, vh + badr);
            ldm4t(b_l, vl + badr);
#pragma unroll
            for (int hf = 0; hf < 2; hf++) {
                float* c = O[nb * 2 + hf];
                uint32_t bhh[2] = {b_h[hf * 2], b_h[hf * 2 + 1]};
                uint32_t bll[2] = {b_l[hf * 2], b_l[hf * 2 + 1]};
                mma16816(c, p_h[j], bhh);
                mma16816(c, p_h[j], bll);
                mma16816(c, p_l[j], bhh);
            }
        }
    }

    // ---- store O (rows = q, cols = d)
    float* Op = Og + base + (w * 16 + (lane >> 2)) * 64 + (lane & 3) * 2;
#pragma unroll
    for (int nf = 0; nf < 8; nf++) {
        *(float2*)(Op + nf * 8)          = make_float2(O[nf][0], O[nf][1]);
        *(float2*)(Op + 8 * 64 + nf * 8) = make_float2(O[nf][2], O[nf][3]);
    }
}

// ---------------------------------------------------------------------------
// Reduce NSPLIT split-K partials + bias -> out (512x512).
// ---------------------------------------------------------------------------
__global__ void reduce_out_kernel(const float4* __restrict__ part,
                                  const float4* __restrict__ bo4,
                                  float4* __restrict__ out)
{
    int i = blockIdx.x * 256 + threadIdx.x;     // 0..65535
    float4 s = bo4[i & 127];
#pragma unroll
    for (int p = 0; p < NSPLIT; p++) {
        float4 v = part[(size_t)p * 65536 + i];
        s.x += v.x; s.y += v.y; s.z += v.z; s.w += v.w;
    }
    out[i] = s;
}

// ---------------------------------------------------------------------------
extern "C" void kernel_launch(void* const* d_in, const int* in_sizes, int n_in,
                              void* d_out, int out_size)
{
    const float* x  = (const float*)d_in[0];
    const float* z  = (const float*)d_in[1];
    const float* Wq = (const float*)d_in[2];
    const float* bq = (const float*)d_in[3];
    const float* Wk = (const float*)d_in[4];
    const float* bk = (const float*)d_in[5];
    const float* Wv = (const float*)d_in[6];
    const float* bv = (const float*)d_in[7];
    const float* Wo = (const float*)d_in[8];
    const float* bo = (const float*)d_in[9];
    float* out = (float*)d_out;

    float *Qd, *Kd, *Vd, *AOd;
    cudaGetSymbolAddress((void**)&Qd,  g_Q);
    cudaGetSymbolAddress((void**)&Kd,  g_K);
    cudaGetSymbolAddress((void**)&Vd,  g_V);
    cudaGetSymbolAddress((void**)&AOd, g_AO);

    static bool attr_set = false;
    if (!attr_set) {
        cudaFuncSetAttribute(attn_mma_kernel,
                             cudaFuncAttributeMaxDynamicSharedMemorySize, 55296);
        attr_set = true;
    }

    // QKV projections
    dim3 gQKV(DTOT / 128, TOK / 128, 1);
    gemm_mma_kernel<<<gQKV, 512>>>(z, 256, Wq, DTOT, bq, Qd, DTOT, 0, 256);
    gemm_mma_kernel<<<gQKV, 512>>>(x, 512, Wk, DTOT, bk, Kd, DTOT, 0, 512);
    gemm_mma_kernel<<<gQKV, 512>>>(x, 512, Wv, DTOT, bv, Vd, DTOT, 0, 512);

    // Attention: 4096 heads
    attn_mma_kernel<<<4096, 128, 55296>>>(Qd, Kd, Vd, AOd);

    // Output projection: split-K partials into g_Q, then reduce (+bias)
    float* Part = Qd;
    dim3 gO(512 / 128, 512 / 128, NSPLIT);
    gemm_mma_kernel<<<gO, 512>>>(AOd, DTOT, Wo, 512, nullptr,
                                 Part, 512, (size_t)512 * 512, DTOT / NSPLIT);

    reduce_out_kernel<<<256, 256>>>((const float4*)Part, (const float4*)bo,
                                    (float4*)out);
}

// round 5
// speedup vs baseline: 2.1323x; 1.2937x over previous
#include <cuda_runtime.h>
#include <cuda_fp16.h>
#include <cstdint>

// ---------------------------------------------------------------------------
//   x: [512,512]  z: [512,256]
//   Wq: [256,32768]  Wk/Wv: [512,32768]  Wo: [32768,512]
// ---------------------------------------------------------------------------
#define TOK   512
#define DTOT  32768
#define NSPLIT 32

__device__ float g_Q [TOK * (size_t)DTOT];   // Q; reused as split-K partials
__device__ float g_K [TOK * (size_t)DTOT];
__device__ float g_V [TOK * (size_t)DTOT];
__device__ float g_AO[TOK * (size_t)DTOT];

// ---------------------------------------------------------------------------
// helpers (family-portable: ldmatrix + mma.sync fp16, fp32 accum)
// ---------------------------------------------------------------------------
__device__ __forceinline__ uint32_t smem_u32(const void* p) {
    uint32_t a;
    asm("{ .reg .u64 t; cvta.to.shared.u64 t, %1; cvt.u32.u64 %0, t; }" : "=r"(a) : "l"(p));
    return a;
}
__device__ __forceinline__ void ldm4(uint32_t r[4], uint32_t addr) {
    asm volatile("ldmatrix.sync.aligned.m8n8.x4.shared.b16 {%0,%1,%2,%3}, [%4];"
                 : "=r"(r[0]), "=r"(r[1]), "=r"(r[2]), "=r"(r[3]) : "r"(addr));
}
__device__ __forceinline__ void ldm4t(uint32_t r[4], uint32_t addr) {
    asm volatile("ldmatrix.sync.aligned.m8n8.x4.trans.shared.b16 {%0,%1,%2,%3}, [%4];"
                 : "=r"(r[0]), "=r"(r[1]), "=r"(r[2]), "=r"(r[3]) : "r"(addr));
}
__device__ __forceinline__ void mma16816(float c[4], const uint32_t a[4], const uint32_t b[2]) {
    asm volatile(
        "mma.sync.aligned.m16n8k16.row.col.f32.f16.f16.f32 "
        "{%0,%1,%2,%3}, {%4,%5,%6,%7}, {%8,%9}, {%0,%1,%2,%3};"
        : "+f"(c[0]), "+f"(c[1]), "+f"(c[2]), "+f"(c[3])
        : "r"(a[0]), "r"(a[1]), "r"(a[2]), "r"(a[3]), "r"(b[0]), "r"(b[1]));
}
// pack two floats as f16x2 (lo = e0, hi = e1)
__device__ __forceinline__ uint32_t pack2(float e0, float e1) {
    uint32_t r;
    asm("cvt.rn.f16x2.f32 %0, %1, %2;" : "=r"(r) : "f"(e1), "f"(e0));
    return r;
}

union Pack8 { unsigned long long u64; __half h[4]; };
__device__ __forceinline__ void split2(float v, __half& h, __half& l) {
    h = __float2half_rn(v);
    l = __float2half_rn(v - __half2float(h));
}
__device__ __forceinline__ unsigned long long round4(float4 v) {
    Pack8 p;
    p.h[0] = __float2half_rn(v.x);
    p.h[1] = __float2half_rn(v.y);
    p.h[2] = __float2half_rn(v.z);
    p.h[3] = __float2half_rn(v.w);
    return p.u64;
}

// ---------------------------------------------------------------------------
// GEMM C[M,N] = A[M,K] @ B[K,N] (+bias), fp16 split-A (Ah+Al) x rounded-B.
// 512 threads, block tile 128x128, BK=32; warp tile 32x32 (warp grid 4x4).
// grid: (N/128, M/128, splits); C += z*csplit; ksize = K per split.
// ---------------------------------------------------------------------------
#define LDA_S 40    // fp16 elems per A smem row (32 + 8 pad)
#define LDB_S 136   // fp16 elems per B smem row (128 + 8 pad)

__global__ __launch_bounds__(512)
void gemm_mma_kernel(const float* __restrict__ A, int lda,
                     const float* __restrict__ B, int ldb,
                     const float* __restrict__ bias,
                     float* __restrict__ C, int ldc,
                     size_t csplit, int ksize)
{
    __shared__ __align__(16) __half Ah[128 * LDA_S];
    __shared__ __align__(16) __half Al[128 * LDA_S];
    __shared__ __align__(16) __half Bh[32 * LDB_S];

    const int tid = threadIdx.x, lane = tid & 31, wid = tid >> 5;
    const int wm = wid & 3, wn = wid >> 2;
    const int n0 = blockIdx.x << 7, m0 = blockIdx.y << 7;
    const int kbeg = blockIdx.z * ksize;
    C += (size_t)blockIdx.z * csplit;

    float acc[2][4][4];
#pragma unroll
    for (int i = 0; i < 2; i++)
#pragma unroll
        for (int j = 0; j < 4; j++)
#pragma unroll
            for (int k = 0; k < 4; k++) acc[i][j][k] = 0.f;

    const int lr = lane & 15, lc = lane >> 4;
    const uint32_t ahb = smem_u32(Ah), alb = smem_u32(Al);
    const uint32_t bhb = smem_u32(Bh);

    const int arow = tid >> 3, ac4 = (tid & 7) << 2;   // A: 64 rows/pass, 2 passes
    const int brow = tid >> 5, bc4 = (tid & 31) << 2;  // B: 16 rows/pass, 2 passes

    const float* Ap0 = A + (size_t)(m0 + arow) * lda + kbeg + ac4;
    const float* Ap1 = Ap0 + (size_t)64 * lda;
    const float* Bp0 = B + (size_t)(kbeg + brow) * ldb + n0 + bc4;
    const float* Bp1 = Bp0 + (size_t)16 * ldb;

    float4 pa0 = *(const float4*)Ap0;
    float4 pa1 = *(const float4*)Ap1;
    float4 pb0 = *(const float4*)Bp0;
    float4 pb1 = *(const float4*)Bp1;

    const int nch = ksize >> 5;
    for (int ch = 0; ch < nch; ch++) {
        // smem is free here (sync at end of previous iteration)
        {
            Pack8 ph, pl;
            split2(pa0.x, ph.h[0], pl.h[0]);
            split2(pa0.y, ph.h[1], pl.h[1]);
            split2(pa0.z, ph.h[2], pl.h[2]);
            split2(pa0.w, ph.h[3], pl.h[3]);
            *(unsigned long long*)((char*)Ah + 2 * (arow * LDA_S + ac4)) = ph.u64;
            *(unsigned long long*)((char*)Al + 2 * (arow * LDA_S + ac4)) = pl.u64;
            split2(pa1.x, ph.h[0], pl.h[0]);
            split2(pa1.y, ph.h[1], pl.h[1]);
            split2(pa1.z, ph.h[2], pl.h[2]);
            split2(pa1.w, ph.h[3], pl.h[3]);
            *(unsigned long long*)((char*)Ah + 2 * ((arow + 64) * LDA_S + ac4)) = ph.u64;
            *(unsigned long long*)((char*)Al + 2 * ((arow + 64) * LDA_S + ac4)) = pl.u64;
            *(unsigned long long*)((char*)Bh + 2 * (brow * LDB_S + bc4)) = round4(pb0);
            *(unsigned long long*)((char*)Bh + 2 * ((brow + 16) * LDB_S + bc4)) = round4(pb1);
        }
        __syncthreads();

        if (ch + 1 < nch) {        // prefetch next chunk while MMAs run
            pa0 = *(const float4*)(Ap0 + (ch + 1) * 32);
            pa1 = *(const float4*)(Ap1 + (ch + 1) * 32);
            pb0 = *(const float4*)(Bp0 + (size_t)(ch + 1) * 32 * ldb);
            pb1 = *(const float4*)(Bp1 + (size_t)(ch + 1) * 32 * ldb);
        }

#pragma unroll
        for (int ks = 0; ks < 2; ks++) {
            uint32_t a_h[2][4], a_l[2][4];
#pragma unroll
            for (int mf = 0; mf < 2; mf++) {
                uint32_t adr = 2 * ((wm * 32 + mf * 16 + lr) * LDA_S + ks * 16 + lc * 8);
                ldm4(a_h[mf], ahb + adr);
                ldm4(a_l[mf], alb + adr);
            }
            uint32_t b_h[2][4];
#pragma unroll
            for (int nb = 0; nb < 2; nb++) {
                uint32_t adr = 2 * ((ks * 16 + lr) * LDB_S + wn * 32 + nb * 16 + lc * 8);
                ldm4t(b_h[nb], bhb + adr);
            }
#pragma unroll
            for (int mf = 0; mf < 2; mf++)
#pragma unroll
                for (int nb = 0; nb < 2; nb++)
#pragma unroll
                    for (int hf = 0; hf < 2; hf++) {
                        float* c = acc[mf][nb * 2 + hf];
                        uint32_t bhh[2] = {b_h[nb][hf * 2], b_h[nb][hf * 2 + 1]};
                        mma16816(c, a_h[mf], bhh);
                        mma16816(c, a_l[mf], bhh);
                    }
        }
        __syncthreads();
    }

    const int rbase = m0 + wm * 32 + (lane >> 2);
    const int cb = n0 + wn * 32 + (lane & 3) * 2;
#pragma unroll
    for (int mf = 0; mf < 2; mf++)
#pragma unroll
        for (int nf = 0; nf < 4; nf++) {
            int rr = rbase + mf * 16;
            int cc = cb + nf * 8;
            float2 v0 = make_float2(acc[mf][nf][0], acc[mf][nf][1]);
            float2 v1 = make_float2(acc[mf][nf][2], acc[mf][nf][3]);
            if (bias) {
                float2 bb = *(const float2*)(bias + cc);
                v0.x += bb.x; v0.y += bb.y;
                v1.x += bb.x; v1.y += bb.y;
            }
            *(float2*)(C + (size_t)rr * ldc + cc) = v0;
            *(float2*)(C + (size_t)(rr + 8) * ldc + cc) = v1;
        }
}

// ---------------------------------------------------------------------------
// Tensor-core attention, fp16: Q split hi/lo, K and V rounded, P single fp16.
// One head (64x64) per 128-thread block; warp w owns q-rows 16w..16w+15.
// ---------------------------------------------------------------------------
#define ALD 72   // fp16 elems per smem row (64 + 8 pad)

__global__ __launch_bounds__(128)
void attn_mma_kernel(const float* __restrict__ Qg, const float* __restrict__ Kg,
                     const float* __restrict__ Vg, float* __restrict__ Og)
{
    __shared__ __align__(16) __half QH[64 * ALD];
    __shared__ __align__(16) __half QL[64 * ALD];
    __shared__ __align__(16) __half KH[64 * ALD];
    __shared__ __align__(16) __half VH[64 * ALD];

    const int tid = threadIdx.x, lane = tid & 31, w = tid >> 5;
    const size_t base = (size_t)blockIdx.x * 4096;

    // Q: split hi/lo
    for (int f = tid; f < 1024; f += 128) {
        int r = f >> 4, c = (f & 15) << 2;
        float4 v = *(const float4*)(Qg + base + r * 64 + c);
        Pack8 ph, pl;
        split2(v.x, ph.h[0], pl.h[0]);
        split2(v.y, ph.h[1], pl.h[1]);
        split2(v.z, ph.h[2], pl.h[2]);
        split2(v.w, ph.h[3], pl.h[3]);
        *(unsigned long long*)((char*)QH + 2 * (r * ALD + c)) = ph.u64;
        *(unsigned long long*)((char*)QL + 2 * (r * ALD + c)) = pl.u64;
    }
    // K, V: rounded
    for (int f = tid; f < 1024; f += 128) {
        int r = f >> 4, c = (f & 15) << 2;
        *(unsigned long long*)((char*)KH + 2 * (r * ALD + c)) =
            round4(*(const float4*)(Kg + base + r * 64 + c));
        *(unsigned long long*)((char*)VH + 2 * (r * ALD + c)) =
            round4(*(const float4*)(Vg + base + r * 64 + c));
    }
    __syncthreads();

    const int lr = lane & 15, lc = lane >> 4;
    const uint32_t qh = smem_u32(QH), ql = smem_u32(QL);
    const uint32_t kh = smem_u32(KH), vh = smem_u32(VH);

    // ---- S = Q @ K^T
    float S[8][4];
#pragma unroll
    for (int i = 0; i < 8; i++)
#pragma unroll
        for (int j = 0; j < 4; j++) S[i][j] = 0.f;

#pragma unroll
    for (int ks = 0; ks < 4; ks++) {
        uint32_t a_h[4], a_l[4];
        uint32_t adr = 2 * ((w * 16 + lr) * ALD + ks * 16 + lc * 8);
        ldm4(a_h, qh + adr);
        ldm4(a_l, ql + adr);
#pragma unroll
        for (int nb = 0; nb < 4; nb++) {
            uint32_t badr = 2 * ((nb * 16 + (lane & 7) + (lane >> 4) * 8) * ALD
                                 + ks * 16 + ((lane >> 3) & 1) * 8);
            uint32_t b_h[4];
            ldm4(b_h, kh + badr);
#pragma unroll
            for (int hf = 0; hf < 2; hf++) {
                float* c = S[nb * 2 + hf];
                uint32_t bhh[2] = {b_h[hf * 2], b_h[hf * 2 + 1]};
                mma16816(c, a_h, bhh);
                mma16816(c, a_l, bhh);
            }
        }
    }

    // ---- softmax in fragments (rows lane>>2 and lane>>2+8)
    float mlo = -1e30f, mhi = -1e30f;
#pragma unroll
    for (int nf = 0; nf < 8; nf++) {
        S[nf][0] *= 0.125f; S[nf][1] *= 0.125f;
        S[nf][2] *= 0.125f; S[nf][3] *= 0.125f;
        mlo = fmaxf(mlo, fmaxf(S[nf][0], S[nf][1]));
        mhi = fmaxf(mhi, fmaxf(S[nf][2], S[nf][3]));
    }
    mlo = fmaxf(mlo, __shfl_xor_sync(0xffffffffu, mlo, 1));
    mlo = fmaxf(mlo, __shfl_xor_sync(0xffffffffu, mlo, 2));
    mhi = fmaxf(mhi, __shfl_xor_sync(0xffffffffu, mhi, 1));
    mhi = fmaxf(mhi, __shfl_xor_sync(0xffffffffu, mhi, 2));

    float slo = 0.f, shi = 0.f;
#pragma unroll
    for (int nf = 0; nf < 8; nf++) {
        S[nf][0] = __expf(S[nf][0] - mlo); slo += S[nf][0];
        S[nf][1] = __expf(S[nf][1] - mlo); slo += S[nf][1];
        S[nf][2] = __expf(S[nf][2] - mhi); shi += S[nf][2];
        S[nf][3] = __expf(S[nf][3] - mhi); shi += S[nf][3];
    }
    slo += __shfl_xor_sync(0xffffffffu, slo, 1);
    slo += __shfl_xor_sync(0xffffffffu, slo, 2);
    shi += __shfl_xor_sync(0xffffffffu, shi, 1);
    shi += __shfl_xor_sync(0xffffffffu, shi, 2);
    const float ilo = 1.f / slo, ihi = 1.f / shi;
#pragma unroll
    for (int nf = 0; nf < 8; nf++) {
        S[nf][0] *= ilo; S[nf][1] *= ilo;
        S[nf][2] *= ihi; S[nf][3] *= ihi;
    }

    // ---- P fragments (single fp16; c-frag -> a-frag identity layout)
    uint32_t p_h[4][4];
#pragma unroll
    for (int j = 0; j < 4; j++) {
#pragma unroll
        for (int q = 0; q < 2; q++) {
            const float* s = (q == 0) ? S[2 * j] : S[2 * j + 1];
            p_h[j][q * 2 + 0] = pack2(s[0], s[1]);
            p_h[j][q * 2 + 1] = pack2(s[2], s[3]);
        }
    }

    // ---- O = P @ V
    float O[8][4];
#pragma unroll
    for (int i = 0; i < 8; i++)
#pragma unroll
        for (int j = 0; j < 4; j++) O[i][j] = 0.f;

#pragma unroll
    for (int j = 0; j < 4; j++) {
#pragma unroll
        for (int nb = 0; nb < 4; nb++) {
            uint32_t badr = 2 * ((j * 16 + lr) * ALD + nb * 16 + lc * 8);
            uint32_t b_h[4];
            ldm4t(b_h, vh + badr);
#pragma unroll
            for (int hf = 0; hf < 2; hf++) {
                float* c = O[nb * 2 + hf];
                uint32_t bhh[2] = {b_h[hf * 2], b_h[hf * 2 + 1]};
                mma16816(c, p_h[j], bhh);
            }
        }
    }

    // ---- store O
    float* Op = Og + base + (w * 16 + (lane >> 2)) * 64 + (lane & 3) * 2;
#pragma unroll
    for (int nf = 0; nf < 8; nf++) {
        *(float2*)(Op + nf * 8)          = make_float2(O[nf][0], O[nf][1]);
        *(float2*)(Op + 8 * 64 + nf * 8) = make_float2(O[nf][2], O[nf][3]);
    }
}

// ---------------------------------------------------------------------------
// Reduce NSPLIT split-K partials + bias -> out (512x512).
// ---------------------------------------------------------------------------
__global__ void reduce_out_kernel(const float4* __restrict__ part,
                                  const float4* __restrict__ bo4,
                                  float4* __restrict__ out)
{
    int i = blockIdx.x * 256 + threadIdx.x;     // 0..65535
    float4 s = bo4[i & 127];
#pragma unroll
    for (int p = 0; p < NSPLIT; p++) {
        float4 v = part[(size_t)p * 65536 + i];
        s.x += v.x; s.y += v.y; s.z += v.z; s.w += v.w;
    }
    out[i] = s;
}

// ---------------------------------------------------------------------------
extern "C" void kernel_launch(void* const* d_in, const int* in_sizes, int n_in,
                              void* d_out, int out_size)
{
    const float* x  = (const float*)d_in[0];
    const float* z  = (const float*)d_in[1];
    const float* Wq = (const float*)d_in[2];
    const float* bq = (const float*)d_in[3];
    const float* Wk = (const float*)d_in[4];
    const float* bk = (const float*)d_in[5];
    const float* Wv = (const float*)d_in[6];
    const float* bv = (const float*)d_in[7];
    const float* Wo = (const float*)d_in[8];
    const float* bo = (const float*)d_in[9];
    float* out = (float*)d_out;

    float *Qd, *Kd, *Vd, *AOd;
    cudaGetSymbolAddress((void**)&Qd,  g_Q);
    cudaGetSymbolAddress((void**)&Kd,  g_K);
    cudaGetSymbolAddress((void**)&Vd,  g_V);
    cudaGetSymbolAddress((void**)&AOd, g_AO);

    // QKV projections
    dim3 gQKV(DTOT / 128, TOK / 128, 1);
    gemm_mma_kernel<<<gQKV, 512>>>(z, 256, Wq, DTOT, bq, Qd, DTOT, 0, 256);
    gemm_mma_kernel<<<gQKV, 512>>>(x, 512, Wk, DTOT, bk, Kd, DTOT, 0, 512);
    gemm_mma_kernel<<<gQKV, 512>>>(x, 512, Wv, DTOT, bv, Vd, DTOT, 0, 512);

    // Attention: 4096 heads
    attn_mma_kernel<<<4096, 128>>>(Qd, Kd, Vd, AOd);

    // Output projection: split-K partials into g_Q, then reduce (+bias)
    float* Part = Qd;
    dim3 gO(512 / 128, 512 / 128, NSPLIT);
    gemm_mma_kernel<<<gO, 512>>>(AOd, DTOT, Wo, 512, nullptr,
                                 Part, 512, (size_t)512 * 512, DTOT / NSPLIT);

    reduce_out_kernel<<<256, 256>>>((const float4*)Part, (const float4*)bo,
                                    (float4*)out);
}

// round 6
// speedup vs baseline: 2.7219x; 1.2765x over previous
#include <cuda_runtime.h>
#include <cuda_fp16.h>
#include <cstdint>

// ---------------------------------------------------------------------------
//   x: [512,512]  z: [512,256]
//   Wq: [256,32768]  Wk/Wv: [512,32768]  Wo: [32768,512]
// ---------------------------------------------------------------------------
#define TOK   512
#define DTOT  32768
#define NSPLIT 32

typedef unsigned long long ull;

__device__ float  g_Q [TOK * (size_t)DTOT];   // Q fp32; reused as split-K partials
__device__ float  g_K [TOK * (size_t)DTOT];
__device__ float  g_V [TOK * (size_t)DTOT];
__device__ __half g_AOh[TOK * (size_t)DTOT];  // attention output hi
__device__ __half g_AOl[TOK * (size_t)DTOT];  // attention output lo
__device__ __half g_xh[512 * 512], g_xl[512 * 512];
__device__ __half g_zh[512 * 256], g_zl[512 * 256];

// ---------------------------------------------------------------------------
// helpers (family-portable: ldmatrix + mma.sync fp16, fp32 accum)
// ---------------------------------------------------------------------------
__device__ __forceinline__ uint32_t smem_u32(const void* p) {
    uint32_t a;
    asm("{ .reg .u64 t; cvta.to.shared.u64 t, %1; cvt.u32.u64 %0, t; }" : "=r"(a) : "l"(p));
    return a;
}
__device__ __forceinline__ void ldm4(uint32_t r[4], uint32_t addr) {
    asm volatile("ldmatrix.sync.aligned.m8n8.x4.shared.b16 {%0,%1,%2,%3}, [%4];"
                 : "=r"(r[0]), "=r"(r[1]), "=r"(r[2]), "=r"(r[3]) : "r"(addr));
}
__device__ __forceinline__ void ldm4t(uint32_t r[4], uint32_t addr) {
    asm volatile("ldmatrix.sync.aligned.m8n8.x4.trans.shared.b16 {%0,%1,%2,%3}, [%4];"
                 : "=r"(r[0]), "=r"(r[1]), "=r"(r[2]), "=r"(r[3]) : "r"(addr));
}
__device__ __forceinline__ void mma16816(float c[4], const uint32_t a[4], const uint32_t b[2]) {
    asm volatile(
        "mma.sync.aligned.m16n8k16.row.col.f32.f16.f16.f32 "
        "{%0,%1,%2,%3}, {%4,%5,%6,%7}, {%8,%9}, {%0,%1,%2,%3};"
        : "+f"(c[0]), "+f"(c[1]), "+f"(c[2]), "+f"(c[3])
        : "r"(a[0]), "r"(a[1]), "r"(a[2]), "r"(a[3]), "r"(b[0]), "r"(b[1]));
}
// pack two floats as f16x2 (lo half = e0, hi half = e1)
__device__ __forceinline__ uint32_t pack2(float e0, float e1) {
    uint32_t r;
    asm("cvt.rn.f16x2.f32 %0, %1, %2;" : "=r"(r) : "f"(e1), "f"(e0));
    return r;
}

union Pack8 { ull u64; __half h[4]; };
__device__ __forceinline__ void split2(float v, __half& h, __half& l) {
    h = __float2half_rn(v);
    l = __float2half_rn(v - __half2float(h));
}
__device__ __forceinline__ ull round4(float4 v) {
    Pack8 p;
    p.h[0] = __float2half_rn(v.x);
    p.h[1] = __float2half_rn(v.y);
    p.h[2] = __float2half_rn(v.z);
    p.h[3] = __float2half_rn(v.w);
    return p.u64;
}

// ---------------------------------------------------------------------------
// fp32 -> fp16 hi/lo split (activations, once per launch)
// ---------------------------------------------------------------------------
__global__ void conv_split_kernel(const float4* __restrict__ src,
                                  ull* __restrict__ h, ull* __restrict__ l, int n4)
{
    int i = blockIdx.x * 256 + threadIdx.x;
    if (i >= n4) return;
    float4 v = src[i];
    Pack8 ph, pl;
    split2(v.x, ph.h[0], pl.h[0]);
    split2(v.y, ph.h[1], pl.h[1]);
    split2(v.z, ph.h[2], pl.h[2]);
    split2(v.w, ph.h[3], pl.h[3]);
    h[i] = ph.u64;
    l[i] = pl.u64;
}

// ---------------------------------------------------------------------------
// GEMM C = A @ B (+bias): A given as pre-split fp16 hi/lo, B fp32 rounded in-loop.
// 512 threads, 128x128 tile, BK=32, warp tile 32x32 (4x4 warps).
// Double-buffered smem; reg prefetch 2 chunks ahead.
// dynamic smem layout (bytes):
//   Ah stage s : s*10240            (128 rows x 40 halves)
//   Al stage s : 20480 + s*10240
//   Bh stage s : 40960 + s*8704     (32 rows x 136 halves)
// total 58368
// ---------------------------------------------------------------------------
#define LDA_S 40
#define LDB_S 136
#define GSMEM 58368

__global__ __launch_bounds__(512)
void gemm_mma2_kernel(const __half* __restrict__ Ahg, const __half* __restrict__ Alg, int lda,
                      const float* __restrict__ B, int ldb,
                      const float* __restrict__ bias,
                      float* __restrict__ C, int ldc,
                      size_t csplit, int ksize)
{
    extern __shared__ __align__(16) char dsm[];
    const int tid = threadIdx.x, lane = tid & 31, wid = tid >> 5;
    const int wm = wid & 3, wn = wid >> 2;
    const int n0 = blockIdx.x << 7, m0 = blockIdx.y << 7;
    const int kbeg = blockIdx.z * ksize;
    C += (size_t)blockIdx.z * csplit;

    const uint32_t smb = smem_u32(dsm);

    float acc[2][4][4];
#pragma unroll
    for (int i = 0; i < 2; i++)
#pragma unroll
        for (int j = 0; j < 4; j++)
#pragma unroll
            for (int k = 0; k < 4; k++) acc[i][j][k] = 0.f;

    const int lr = lane & 15, lc = lane >> 4;

    const int a_r = tid >> 2, a_c = (tid & 3) << 3;   // A: 128 rows x 32 halves
    const int b_r = tid >> 5, b_c = (tid & 31) << 2;  // B: 32 rows x 128 floats

    const __half* Aph = Ahg + (size_t)(m0 + a_r) * lda + kbeg + a_c;
    const __half* Apl = Alg + (size_t)(m0 + a_r) * lda + kbeg + a_c;
    const float*  Bp0 = B + (size_t)(kbeg + b_r) * ldb + n0 + b_c;
    const float*  Bp1 = Bp0 + (size_t)16 * ldb;

    uint4 rah, ral;
    float4 rb0, rb1;

#define LDREGS(ch) do { \
    rah = *(const uint4*)(Aph + (ch) * 32); \
    ral = *(const uint4*)(Apl + (ch) * 32); \
    rb0 = *(const float4*)(Bp0 + (size_t)(ch) * 32 * ldb); \
    rb1 = *(const float4*)(Bp1 + (size_t)(ch) * 32 * ldb); } while (0)

#define STOREST(s) do { \
    *(uint4*)(dsm + (s) * 10240 + 2 * (a_r * LDA_S + a_c)) = rah; \
    *(uint4*)(dsm + 20480 + (s) * 10240 + 2 * (a_r * LDA_S + a_c)) = ral; \
    uint2 p0, p1; \
    p0.x = pack2(rb0.x, rb0.y); p0.y = pack2(rb0.z, rb0.w); \
    p1.x = pack2(rb1.x, rb1.y); p1.y = pack2(rb1.z, rb1.w); \
    *(uint2*)(dsm + 40960 + (s) * 8704 + 2 * (b_r * LDB_S + b_c)) = p0; \
    *(uint2*)(dsm + 40960 + (s) * 8704 + 2 * ((b_r + 16) * LDB_S + b_c)) = p1; } while (0)

    const int nch = ksize >> 5;
    LDREGS(0);
    STOREST(0);
    if (nch > 1) LDREGS(1);
    __syncthreads();

    for (int ch = 0; ch < nch; ch++) {
        const int cur = ch & 1;
        if (ch + 1 < nch) STOREST(cur ^ 1);
        if (ch + 2 < nch) LDREGS(ch + 2);

        const uint32_t ahb = smb + cur * 10240;
        const uint32_t alb = smb + 20480 + cur * 10240;
        const uint32_t bhb = smb + 40960 + cur * 8704;

#pragma unroll
        for (int ks = 0; ks < 2; ks++) {
            uint32_t a_h[2][4], a_l[2][4];
#pragma unroll
            for (int mf = 0; mf < 2; mf++) {
                uint32_t adr = 2 * ((wm * 32 + mf * 16 + lr) * LDA_S + ks * 16 + lc * 8);
                ldm4(a_h[mf], ahb + adr);
                ldm4(a_l[mf], alb + adr);
            }
            uint32_t b_h[2][4];
#pragma unroll
            for (int nb = 0; nb < 2; nb++) {
                uint32_t adr = 2 * ((ks * 16 + lr) * LDB_S + wn * 32 + nb * 16 + lc * 8);
                ldm4t(b_h[nb], bhb + adr);
            }
#pragma unroll
            for (int mf = 0; mf < 2; mf++)
#pragma unroll
                for (int nb = 0; nb < 2; nb++)
#pragma unroll
                    for (int hf = 0; hf < 2; hf++) {
                        float* c = acc[mf][nb * 2 + hf];
                        uint32_t bhh[2] = {b_h[nb][hf * 2], b_h[nb][hf * 2 + 1]};
                        mma16816(c, a_h[mf], bhh);
                        mma16816(c, a_l[mf], bhh);
                    }
        }
        __syncthreads();
    }
#undef LDREGS
#undef STOREST

    const int rbase = m0 + wm * 32 + (lane >> 2);
    const int cb = n0 + wn * 32 + (lane & 3) * 2;
#pragma unroll
    for (int mf = 0; mf < 2; mf++)
#pragma unroll
        for (int nf = 0; nf < 4; nf++) {
            int rr = rbase + mf * 16;
            int cc = cb + nf * 8;
            float2 v0 = make_float2(acc[mf][nf][0], acc[mf][nf][1]);
            float2 v1 = make_float2(acc[mf][nf][2], acc[mf][nf][3]);
            if (bias) {
                float2 bb = *(const float2*)(bias + cc);
                v0.x += bb.x; v0.y += bb.y;
                v1.x += bb.x; v1.y += bb.y;
            }
            *(float2*)(C + (size_t)rr * ldc + cc) = v0;
            *(float2*)(C + (size_t)(rr + 8) * ldc + cc) = v1;
        }
}

// ---------------------------------------------------------------------------
// Tensor-core attention: Q split hi/lo, K/V rounded; O written as fp16 hi/lo.
// One head (64x64) per 128-thread block; warp w owns q-rows 16w..16w+15.
// ---------------------------------------------------------------------------
#define ALD 72

__device__ __forceinline__ void emit_hl(__half* AOh, __half* AOl, size_t idx,
                                        float a, float b) {
    float ha = __half2float(__float2half_rn(a));
    float hb = __half2float(__float2half_rn(b));
    *(uint32_t*)(AOh + idx) = pack2(a, b);
    *(uint32_t*)(AOl + idx) = pack2(a - ha, b - hb);
}

__global__ __launch_bounds__(128)
void attn_mma_kernel(const float* __restrict__ Qg, const float* __restrict__ Kg,
                     const float* __restrict__ Vg,
                     __half* __restrict__ AOh, __half* __restrict__ AOl)
{
    __shared__ __align__(16) __half QH[64 * ALD];
    __shared__ __align__(16) __half QL[64 * ALD];
    __shared__ __align__(16) __half KH[64 * ALD];
    __shared__ __align__(16) __half VH[64 * ALD];

    const int tid = threadIdx.x, lane = tid & 31, w = tid >> 5;
    const size_t base = (size_t)blockIdx.x * 4096;

    for (int f = tid; f < 1024; f += 128) {
        int r = f >> 4, c = (f & 15) << 2;
        float4 v = *(const float4*)(Qg + base + r * 64 + c);
        Pack8 ph, pl;
        split2(v.x, ph.h[0], pl.h[0]);
        split2(v.y, ph.h[1], pl.h[1]);
        split2(v.z, ph.h[2], pl.h[2]);
        split2(v.w, ph.h[3], pl.h[3]);
        *(ull*)((char*)QH + 2 * (r * ALD + c)) = ph.u64;
        *(ull*)((char*)QL + 2 * (r * ALD + c)) = pl.u64;
    }
    for (int f = tid; f < 1024; f += 128) {
        int r = f >> 4, c = (f & 15) << 2;
        *(ull*)((char*)KH + 2 * (r * ALD + c)) =
            round4(*(const float4*)(Kg + base + r * 64 + c));
        *(ull*)((char*)VH + 2 * (r * ALD + c)) =
            round4(*(const float4*)(Vg + base + r * 64 + c));
    }
    __syncthreads();

    const int lr = lane & 15, lc = lane >> 4;
    const uint32_t qh = smem_u32(QH), ql = smem_u32(QL);
    const uint32_t kh = smem_u32(KH), vh = smem_u32(VH);

    float S[8][4];
#pragma unroll
    for (int i = 0; i < 8; i++)
#pragma unroll
        for (int j = 0; j < 4; j++) S[i][j] = 0.f;

#pragma unroll
    for (int ks = 0; ks < 4; ks++) {
        uint32_t a_h[4], a_l[4];
        uint32_t adr = 2 * ((w * 16 + lr) * ALD + ks * 16 + lc * 8);
        ldm4(a_h, qh + adr);
        ldm4(a_l, ql + adr);
#pragma unroll
        for (int nb = 0; nb < 4; nb++) {
            uint32_t badr = 2 * ((nb * 16 + (lane & 7) + (lane >> 4) * 8) * ALD
                                 + ks * 16 + ((lane >> 3) & 1) * 8);
            uint32_t b_h[4];
            ldm4(b_h, kh + badr);
#pragma unroll
            for (int hf = 0; hf < 2; hf++) {
                float* c = S[nb * 2 + hf];
                uint32_t bhh[2] = {b_h[hf * 2], b_h[hf * 2 + 1]};
                mma16816(c, a_h, bhh);
                mma16816(c, a_l, bhh);
            }
        }
    }

    float mlo = -1e30f, mhi = -1e30f;
#pragma unroll
    for (int nf = 0; nf < 8; nf++) {
        S[nf][0] *= 0.125f; S[nf][1] *= 0.125f;
        S[nf][2] *= 0.125f; S[nf][3] *= 0.125f;
        mlo = fmaxf(mlo, fmaxf(S[nf][0], S[nf][1]));
        mhi = fmaxf(mhi, fmaxf(S[nf][2], S[nf][3]));
    }
    mlo = fmaxf(mlo, __shfl_xor_sync(0xffffffffu, mlo, 1));
    mlo = fmaxf(mlo, __shfl_xor_sync(0xffffffffu, mlo, 2));
    mhi = fmaxf(mhi, __shfl_xor_sync(0xffffffffu, mhi, 1));
    mhi = fmaxf(mhi, __shfl_xor_sync(0xffffffffu, mhi, 2));

    float slo = 0.f, shi = 0.f;
#pragma unroll
    for (int nf = 0; nf < 8; nf++) {
        S[nf][0] = __expf(S[nf][0] - mlo); slo += S[nf][0];
        S[nf][1] = __expf(S[nf][1] - mlo); slo += S[nf][1];
        S[nf][2] = __expf(S[nf][2] - mhi); shi += S[nf][2];
        S[nf][3] = __expf(S[nf][3] - mhi); shi += S[nf][3];
    }
    slo += __shfl_xor_sync(0xffffffffu, slo, 1);
    slo += __shfl_xor_sync(0xffffffffu, slo, 2);
    shi += __shfl_xor_sync(0xffffffffu, shi, 1);
    shi += __shfl_xor_sync(0xffffffffu, shi, 2);
    const float ilo = 1.f / slo, ihi = 1.f / shi;
#pragma unroll
    for (int nf = 0; nf < 8; nf++) {
        S[nf][0] *= ilo; S[nf][1] *= ilo;
        S[nf][2] *= ihi; S[nf][3] *= ihi;
    }

    uint32_t p_h[4][4];
#pragma unroll
    for (int j = 0; j < 4; j++) {
#pragma unroll
        for (int q = 0; q < 2; q++) {
            const float* s = (q == 0) ? S[2 * j] : S[2 * j + 1];
            p_h[j][q * 2 + 0] = pack2(s[0], s[1]);
            p_h[j][q * 2 + 1] = pack2(s[2], s[3]);
        }
    }

    float O[8][4];
#pragma unroll
    for (int i = 0; i < 8; i++)
#pragma unroll
        for (int j = 0; j < 4; j++) O[i][j] = 0.f;

#pragma unroll
    for (int j = 0; j < 4; j++) {
#pragma unroll
        for (int nb = 0; nb < 4; nb++) {
            uint32_t badr = 2 * ((j * 16 + lr) * ALD + nb * 16 + lc * 8);
            uint32_t b_h[4];
            ldm4t(b_h, vh + badr);
#pragma unroll
            for (int hf = 0; hf < 2; hf++) {
                float* c = O[nb * 2 + hf];
                uint32_t bhh[2] = {b_h[hf * 2], b_h[hf * 2 + 1]};
                mma16816(c, p_h[j], bhh);
            }
        }
    }

    // store O as fp16 hi/lo
    const size_t ob = base + (size_t)(w * 16 + (lane >> 2)) * 64 + (lane & 3) * 2;
#pragma unroll
    for (int nf = 0; nf < 8; nf++) {
        emit_hl(AOh, AOl, ob + nf * 8,       O[nf][0], O[nf][1]);
        emit_hl(AOh, AOl, ob + 512 + nf * 8, O[nf][2], O[nf][3]);
    }
}

// ---------------------------------------------------------------------------
// Reduce NSPLIT split-K partials + bias -> out (512x512).
// ---------------------------------------------------------------------------
__global__ void reduce_out_kernel(const float4* __restrict__ part,
                                  const float4* __restrict__ bo4,
                                  float4* __restrict__ out)
{
    int i = blockIdx.x * 256 + threadIdx.x;     // 0..65535
    float4 s = bo4[i & 127];
#pragma unroll
    for (int p = 0; p < NSPLIT; p++) {
        float4 v = part[(size_t)p * 65536 + i];
        s.x += v.x; s.y += v.y; s.z += v.z; s.w += v.w;
    }
    out[i] = s;
}

// ---------------------------------------------------------------------------
extern "C" void kernel_launch(void* const* d_in, const int* in_sizes, int n_in,
                              void* d_out, int out_size)
{
    const float* x  = (const float*)d_in[0];
    const float* z  = (const float*)d_in[1];
    const float* Wq = (const float*)d_in[2];
    const float* bq = (const float*)d_in[3];
    const float* Wk = (const float*)d_in[4];
    const float* bk = (const float*)d_in[5];
    const float* Wv = (const float*)d_in[6];
    const float* bv = (const float*)d_in[7];
    const float* Wo = (const float*)d_in[8];
    const float* bo = (const float*)d_in[9];
    float* out = (float*)d_out;

    float *Qd, *Kd, *Vd;
    __half *AOh, *AOl, *xh, *xl, *zh, *zl;
    cudaGetSymbolAddress((void**)&Qd,  g_Q);
    cudaGetSymbolAddress((void**)&Kd,  g_K);
    cudaGetSymbolAddress((void**)&Vd,  g_V);
    cudaGetSymbolAddress((void**)&AOh, g_AOh);
    cudaGetSymbolAddress((void**)&AOl, g_AOl);
    cudaGetSymbolAddress((void**)&xh,  g_xh);
    cudaGetSymbolAddress((void**)&xl,  g_xl);
    cudaGetSymbolAddress((void**)&zh,  g_zh);
    cudaGetSymbolAddress((void**)&zl,  g_zl);

    cudaFuncSetAttribute(gemm_mma2_kernel,
                         cudaFuncAttributeMaxDynamicSharedMemorySize, GSMEM);

    // Pre-split activations
    conv_split_kernel<<<128, 256>>>((const float4*)z, (ull*)zh, (ull*)zl, 32768);
    conv_split_kernel<<<256, 256>>>((const float4*)x, (ull*)xh, (ull*)xl, 65536);

    // QKV projections
    dim3 gQKV(DTOT / 128, TOK / 128, 1);
    gemm_mma2_kernel<<<gQKV, 512, GSMEM>>>(zh, zl, 256, Wq, DTOT, bq, Qd, DTOT, 0, 256);
    gemm_mma2_kernel<<<gQKV, 512, GSMEM>>>(xh, xl, 512, Wk, DTOT, bk, Kd, DTOT, 0, 512);
    gemm_mma2_kernel<<<gQKV, 512, GSMEM>>>(xh, xl, 512, Wv, DTOT, bv, Vd, DTOT, 0, 512);

    // Attention: 4096 heads; writes AO as fp16 hi/lo
    attn_mma_kernel<<<4096, 128>>>(Qd, Kd, Vd, AOh, AOl);

    // Output projection: split-K partials into g_Q scratch, then reduce (+bias)
    float* Part = Qd;
    dim3 gO(512 / 128, 512 / 128, NSPLIT);
    gemm_mma2_kernel<<<gO, 512, GSMEM>>>(AOh, AOl, DTOT, Wo, 512, nullptr,
                                         Part, 512, (size_t)512 * 512, DTOT / NSPLIT);

    reduce_out_kernel<<<256, 256>>>((const float4*)Part, (const float4*)bo,
                                    (float4*)out);
}

// round 7
// speedup vs baseline: 3.0240x; 1.1110x over previous
#include <cuda_runtime.h>
#include <cuda_fp16.h>
#include <cstdint>

// ---------------------------------------------------------------------------
//   x: [512,512]  z: [512,256]
//   Wq: [256,32768]  Wk/Wv: [512,32768]  Wo: [32768,512]
// ---------------------------------------------------------------------------
#define TOK   512
#define DTOT  32768
#define NSPLIT 32

typedef unsigned long long ull;

__device__ __half g_Qh[TOK * (size_t)DTOT], g_Ql[TOK * (size_t)DTOT];
__device__ __half g_Kh[TOK * (size_t)DTOT];
__device__ __half g_Vh[TOK * (size_t)DTOT];
__device__ __half g_AOh[TOK * (size_t)DTOT], g_AOl[TOK * (size_t)DTOT];
__device__ float  g_part[NSPLIT * 512 * 512];
__device__ __half g_xh[512 * 512], g_xl[512 * 512];
__device__ __half g_zh[512 * 256], g_zl[512 * 256];

// ---------------------------------------------------------------------------
// helpers
// ---------------------------------------------------------------------------
__device__ __forceinline__ uint32_t smem_u32(const void* p) {
    uint32_t a;
    asm("{ .reg .u64 t; cvta.to.shared.u64 t, %1; cvt.u32.u64 %0, t; }" : "=r"(a) : "l"(p));
    return a;
}
__device__ __forceinline__ void ldm4(uint32_t r[4], uint32_t addr) {
    asm volatile("ldmatrix.sync.aligned.m8n8.x4.shared.b16 {%0,%1,%2,%3}, [%4];"
                 : "=r"(r[0]), "=r"(r[1]), "=r"(r[2]), "=r"(r[3]) : "r"(addr));
}
__device__ __forceinline__ void ldm4t(uint32_t r[4], uint32_t addr) {
    asm volatile("ldmatrix.sync.aligned.m8n8.x4.trans.shared.b16 {%0,%1,%2,%3}, [%4];"
                 : "=r"(r[0]), "=r"(r[1]), "=r"(r[2]), "=r"(r[3]) : "r"(addr));
}
__device__ __forceinline__ void mma16816(float c[4], const uint32_t a[4], const uint32_t b[2]) {
    asm volatile(
        "mma.sync.aligned.m16n8k16.row.col.f32.f16.f16.f32 "
        "{%0,%1,%2,%3}, {%4,%5,%6,%7}, {%8,%9}, {%0,%1,%2,%3};"
        : "+f"(c[0]), "+f"(c[1]), "+f"(c[2]), "+f"(c[3])
        : "r"(a[0]), "r"(a[1]), "r"(a[2]), "r"(a[3]), "r"(b[0]), "r"(b[1]));
}
__device__ __forceinline__ uint32_t pack2(float e0, float e1) {   // lo=e0, hi=e1
    uint32_t r;
    asm("cvt.rn.f16x2.f32 %0, %1, %2;" : "=r"(r) : "f"(e1), "f"(e0));
    return r;
}

union Pack8 { ull u64; __half h[4]; };
__device__ __forceinline__ void split2(float v, __half& h, __half& l) {
    h = __float2half_rn(v);
    l = __float2half_rn(v - __half2float(h));
}

// ---------------------------------------------------------------------------
// fp32 -> fp16 hi/lo split (activations)
// ---------------------------------------------------------------------------
__global__ void conv_split_kernel(const float4* __restrict__ src,
                                  ull* __restrict__ h, ull* __restrict__ l, int n4)
{
    int i = blockIdx.x * 256 + threadIdx.x;
    if (i >= n4) return;
    float4 v = src[i];
    Pack8 ph, pl;
    split2(v.x, ph.h[0], pl.h[0]);
    split2(v.y, ph.h[1], pl.h[1]);
    split2(v.z, ph.h[2], pl.h[2]);
    split2(v.w, ph.h[3], pl.h[3]);
    h[i] = ph.u64;
    l[i] = pl.u64;
}

// ---------------------------------------------------------------------------
// GEMM C = A @ B (+bias): A pre-split fp16 hi/lo, B fp32 rounded in-loop.
// 512 threads, block tile 128x256, BK=32; warp tile 32x64 (4x4 warp grid).
// Double-buffered smem, reg prefetch 2 ahead.
// smem bytes: Ah s: s*10240 | Al: 20480 + s*10240 | B: 40960 + s*16896
// mode: 0 = fp32 C (+bias if non-null); 1 = fp16 hi+lo (+bias); 2 = fp16 hi (+bias)
// ---------------------------------------------------------------------------
#define LDA_S 40
#define LDB_S 264
#define ASTG  10240
#define BSTG  16896
#define GSMEM (40960 + 2 * BSTG)

__global__ __launch_bounds__(512)
void gemm_mma3_kernel(const __half* __restrict__ Ahg, const __half* __restrict__ Alg, int lda,
                      const float* __restrict__ B, int ldb,
                      const float* __restrict__ bias, int mode,
                      float* __restrict__ Cf, __half* __restrict__ Ch,
                      __half* __restrict__ Cl, int ldc,
                      size_t csplit, int ksize)
{
    extern __shared__ __align__(16) char dsm[];
    const int tid = threadIdx.x, lane = tid & 31, wid = tid >> 5;
    const int wm = wid & 3, wn = wid >> 2;
    const int n0 = blockIdx.x << 8, m0 = blockIdx.y << 7;
    const int kbeg = blockIdx.z * ksize;
    if (Cf) Cf += (size_t)blockIdx.z * csplit;

    const uint32_t smb = smem_u32(dsm);

    float acc[2][8][4];
#pragma unroll
    for (int i = 0; i < 2; i++)
#pragma unroll
        for (int j = 0; j < 8; j++)
#pragma unroll
            for (int k = 0; k < 4; k++) acc[i][j][k] = 0.f;

    const int lr = lane & 15, lc = lane >> 4;

    const int a_r = tid >> 2, a_c = (tid & 3) << 3;   // A: 128 x 32 halves, 1 uint4/thr
    const int b_r = tid >> 6, b_c = (tid & 63) << 2;  // B: 32 x 256 floats, 4 float4/thr

    const __half* Aph = Ahg + (size_t)(m0 + a_r) * lda + kbeg + a_c;
    const __half* Apl = Alg + (size_t)(m0 + a_r) * lda + kbeg + a_c;
    const float*  Bp  = B + (size_t)(kbeg + b_r) * ldb + n0 + b_c;

    uint4 rah, ral;
    float4 rb[4];

#define LDREGS(ch) do { \
    rah = *(const uint4*)(Aph + (ch) * 32); \
    ral = *(const uint4*)(Apl + (ch) * 32); \
    _Pragma("unroll") \
    for (int p = 0; p < 4; p++) \
        rb[p] = *(const float4*)(Bp + (size_t)((ch) * 32 + p * 8) * ldb); } while (0)

#define STOREST(s) do { \
    *(uint4*)(dsm + (s) * ASTG + 2 * (a_r * LDA_S + a_c)) = rah; \
    *(uint4*)(dsm + 20480 + (s) * ASTG + 2 * (a_r * LDA_S + a_c)) = ral; \
    _Pragma("unroll") \
    for (int p = 0; p < 4; p++) { \
        uint2 pk; \
        pk.x = pack2(rb[p].x, rb[p].y); \
        pk.y = pack2(rb[p].z, rb[p].w); \
        *(uint2*)(dsm + 40960 + (s) * BSTG + 2 * ((b_r + p * 8) * LDB_S + b_c)) = pk; \
    } } while (0)

    const int nch = ksize >> 5;
    LDREGS(0);
    STOREST(0);
    if (nch > 1) LDREGS(1);
    __syncthreads();

    for (int ch = 0; ch < nch; ch++) {
        const int cur = ch & 1;
        if (ch + 1 < nch) STOREST(cur ^ 1);
        if (ch + 2 < nch) LDREGS(ch + 2);

        const uint32_t ahb = smb + cur * ASTG;
        const uint32_t alb = smb + 20480 + cur * ASTG;
        const uint32_t bhb = smb + 40960 + cur * BSTG;

#pragma unroll
        for (int ks = 0; ks < 2; ks++) {
            uint32_t a_h[2][4], a_l[2][4];
#pragma unroll
            for (int mf = 0; mf < 2; mf++) {
                uint32_t adr = 2 * ((wm * 32 + mf * 16 + lr) * LDA_S + ks * 16 + lc * 8);
                ldm4(a_h[mf], ahb + adr);
                ldm4(a_l[mf], alb + adr);
            }
#pragma unroll
            for (int nb = 0; nb < 4; nb++) {
                uint32_t b_f[4];
                uint32_t adr = 2 * ((ks * 16 + lr) * LDB_S + wn * 64 + nb * 16 + lc * 8);
                ldm4t(b_f, bhb + adr);
#pragma unroll
                for (int mf = 0; mf < 2; mf++)
#pragma unroll
                    for (int hf = 0; hf < 2; hf++) {
                        float* c = acc[mf][nb * 2 + hf];
                        uint32_t bb[2] = {b_f[hf * 2], b_f[hf * 2 + 1]};
                        mma16816(c, a_h[mf], bb);
                        mma16816(c, a_l[mf], bb);
                    }
            }
        }
        __syncthreads();
    }
#undef LDREGS
#undef STOREST

    const int rbase = m0 + wm * 32 + (lane >> 2);
    const int cb = n0 + wn * 64 + (lane & 3) * 2;
#pragma unroll
    for (int mf = 0; mf < 2; mf++)
#pragma unroll
        for (int nf = 0; nf < 8; nf++) {
            int rr = rbase + mf * 16;
            int cc = cb + nf * 8;
            float2 v0 = make_float2(acc[mf][nf][0], acc[mf][nf][1]);
            float2 v1 = make_float2(acc[mf][nf][2], acc[mf][nf][3]);
            if (bias) {
                float2 bb = *(const float2*)(bias + cc);
                v0.x += bb.x; v0.y += bb.y;
                v1.x += bb.x; v1.y += bb.y;
            }
            if (mode == 0) {
                *(float2*)(Cf + (size_t)rr * ldc + cc) = v0;
                *(float2*)(Cf + (size_t)(rr + 8) * ldc + cc) = v1;
            } else if (mode == 2) {
                *(uint32_t*)(Ch + (size_t)rr * ldc + cc) = pack2(v0.x, v0.y);
                *(uint32_t*)(Ch + (size_t)(rr + 8) * ldc + cc) = pack2(v1.x, v1.y);
            } else {
                float h0 = __half2float(__float2half_rn(v0.x));
                float h1 = __half2float(__float2half_rn(v0.y));
                float h2 = __half2float(__float2half_rn(v1.x));
                float h3 = __half2float(__float2half_rn(v1.y));
                *(uint32_t*)(Ch + (size_t)rr * ldc + cc) = pack2(v0.x, v0.y);
                *(uint32_t*)(Cl + (size_t)rr * ldc + cc) = pack2(v0.x - h0, v0.y - h1);
                *(uint32_t*)(Ch + (size_t)(rr + 8) * ldc + cc) = pack2(v1.x, v1.y);
                *(uint32_t*)(Cl + (size_t)(rr + 8) * ldc + cc) = pack2(v1.x - h2, v1.y - h3);
            }
        }
}

// ---------------------------------------------------------------------------
// Tensor-core attention, all-fp16 inputs (Q hi/lo, K, V), fp16 hi/lo output.
// One head (64x64) per 128-thread block; warp w owns q-rows 16w..16w+15.
// ---------------------------------------------------------------------------
#define ALD 72

__device__ __forceinline__ void emit_hl(__half* AOh, __half* AOl, size_t idx,
                                        float a, float b) {
    float ha = __half2float(__float2half_rn(a));
    float hb = __half2float(__float2half_rn(b));
    *(uint32_t*)(AOh + idx) = pack2(a, b);
    *(uint32_t*)(AOl + idx) = pack2(a - ha, b - hb);
}

__global__ __launch_bounds__(128)
void attn_mma_kernel(const __half* __restrict__ Qhg, const __half* __restrict__ Qlg,
                     const __half* __restrict__ Khg, const __half* __restrict__ Vhg,
                     __half* __restrict__ AOh, __half* __restrict__ AOl)
{
    __shared__ __align__(16) __half QH[64 * ALD];
    __shared__ __align__(16) __half QL[64 * ALD];
    __shared__ __align__(16) __half KH[64 * ALD];
    __shared__ __align__(16) __half VH[64 * ALD];

    const int tid = threadIdx.x, lane = tid & 31, w = tid >> 5;
    const size_t base = (size_t)blockIdx.x * 4096;

    // direct fp16 tile copies (512 uint4 per tile, 4 per thread per tile)
#pragma unroll
    for (int i = 0; i < 4; i++) {
        int f = i * 128 + tid;             // 0..511
        int r = f >> 3, c = (f & 7) << 3;
        uint32_t off = 2 * (r * ALD + c);
        size_t g = base + r * 64 + c;
        *(uint4*)((char*)QH + off) = *(const uint4*)(Qhg + g);
        *(uint4*)((char*)QL + off) = *(const uint4*)(Qlg + g);
        *(uint4*)((char*)KH + off) = *(const uint4*)(Khg + g);
        *(uint4*)((char*)VH + off) = *(const uint4*)(Vhg + g);
    }
    __syncthreads();

    const int lr = lane & 15, lc = lane >> 4;
    const uint32_t qh = smem_u32(QH), ql = smem_u32(QL);
    const uint32_t kh = smem_u32(KH), vh = smem_u32(VH);

    float S[8][4];
#pragma unroll
    for (int i = 0; i < 8; i++)
#pragma unroll
        for (int j = 0; j < 4; j++) S[i][j] = 0.f;

#pragma unroll
    for (int ks = 0; ks < 4; ks++) {
        uint32_t a_h[4], a_l[4];
        uint32_t adr = 2 * ((w * 16 + lr) * ALD + ks * 16 + lc * 8);
        ldm4(a_h, qh + adr);
        ldm4(a_l, ql + adr);
#pragma unroll
        for (int nb = 0; nb < 4; nb++) {
            uint32_t badr = 2 * ((nb * 16 + (lane & 7) + (lane >> 4) * 8) * ALD
                                 + ks * 16 + ((lane >> 3) & 1) * 8);
            uint32_t b_h[4];
            ldm4(b_h, kh + badr);
#pragma unroll
            for (int hf = 0; hf < 2; hf++) {
                float* c = S[nb * 2 + hf];
                uint32_t bb[2] = {b_h[hf * 2], b_h[hf * 2 + 1]};
                mma16816(c, a_h, bb);
                mma16816(c, a_l, bb);
            }
        }
    }

    float mlo = -1e30f, mhi = -1e30f;
#pragma unroll
    for (int nf = 0; nf < 8; nf++) {
        S[nf][0] *= 0.125f; S[nf][1] *= 0.125f;
        S[nf][2] *= 0.125f; S[nf][3] *= 0.125f;
        mlo = fmaxf(mlo, fmaxf(S[nf][0], S[nf][1]));
        mhi = fmaxf(mhi, fmaxf(S[nf][2], S[nf][3]));
    }
    mlo = fmaxf(mlo, __shfl_xor_sync(0xffffffffu, mlo, 1));
    mlo = fmaxf(mlo, __shfl_xor_sync(0xffffffffu, mlo, 2));
    mhi = fmaxf(mhi, __shfl_xor_sync(0xffffffffu, mhi, 1));
    mhi = fmaxf(mhi, __shfl_xor_sync(0xffffffffu, mhi, 2));

    float slo = 0.f, shi = 0.f;
#pragma unroll
    for (int nf = 0; nf < 8; nf++) {
        S[nf][0] = __expf(S[nf][0] - mlo); slo += S[nf][0];
        S[nf][1] = __expf(S[nf][1] - mlo); slo += S[nf][1];
        S[nf][2] = __expf(S[nf][2] - mhi); shi += S[nf][2];
        S[nf][3] = __expf(S[nf][3] - mhi); shi += S[nf][3];
    }
    slo += __shfl_xor_sync(0xffffffffu, slo, 1);
    slo += __shfl_xor_sync(0xffffffffu, slo, 2);
    shi += __shfl_xor_sync(0xffffffffu, shi, 1);
    shi += __shfl_xor_sync(0xffffffffu, shi, 2);
    const float ilo = 1.f / slo, ihi = 1.f / shi;
#pragma unroll
    for (int nf = 0; nf < 8; nf++) {
        S[nf][0] *= ilo; S[nf][1] *= ilo;
        S[nf][2] *= ihi; S[nf][3] *= ihi;
    }

    uint32_t p_h[4][4];
#pragma unroll
    for (int j = 0; j < 4; j++) {
#pragma unroll
        for (int q = 0; q < 2; q++) {
            const float* s = (q == 0) ? S[2 * j] : S[2 * j + 1];
            p_h[j][q * 2 + 0] = pack2(s[0], s[1]);
            p_h[j][q * 2 + 1] = pack2(s[2], s[3]);
        }
    }

    float O[8][4];
#pragma unroll
    for (int i = 0; i < 8; i++)
#pragma unroll
        for (int j = 0; j < 4; j++) O[i][j] = 0.f;

#pragma unroll
    for (int j = 0; j < 4; j++) {
#pragma unroll
        for (int nb = 0; nb < 4; nb++) {
            uint32_t badr = 2 * ((j * 16 + lr) * ALD + nb * 16 + lc * 8);
            uint32_t b_h[4];
            ldm4t(b_h, vh + badr);
#pragma unroll
            for (int hf = 0; hf < 2; hf++) {
                float* c = O[nb * 2 + hf];
                uint32_t bb[2] = {b_h[hf * 2], b_h[hf * 2 + 1]};
                mma16816(c, p_h[j], bb);
            }
        }
    }

    const size_t ob = base + (size_t)(w * 16 + (lane >> 2)) * 64 + (lane & 3) * 2;
#pragma unroll
    for (int nf = 0; nf < 8; nf++) {
        emit_hl(AOh, AOl, ob + nf * 8,       O[nf][0], O[nf][1]);
        emit_hl(AOh, AOl, ob + 512 + nf * 8, O[nf][2], O[nf][3]);
    }
}

// ---------------------------------------------------------------------------
// Reduce NSPLIT split-K partials + bias -> out (512x512).
// ---------------------------------------------------------------------------
__global__ void reduce_out_kernel(const float4* __restrict__ part,
                                  const float4* __restrict__ bo4,
                                  float4* __restrict__ out)
{
    int i = blockIdx.x * 256 + threadIdx.x;     // 0..65535
    float4 s = bo4[i & 127];
#pragma unroll
    for (int p = 0; p < NSPLIT; p++) {
        float4 v = part[(size_t)p * 65536 + i];
        s.x += v.x; s.y += v.y; s.z += v.z; s.w += v.w;
    }
    out[i] = s;
}

// ---------------------------------------------------------------------------
extern "C" void kernel_launch(void* const* d_in, const int* in_sizes, int n_in,
                              void* d_out, int out_size)
{
    const float* x  = (const float*)d_in[0];
    const float* z  = (const float*)d_in[1];
    const float* Wq = (const float*)d_in[2];
    const float* bq = (const float*)d_in[3];
    const float* Wk = (const float*)d_in[4];
    const float* bk = (const float*)d_in[5];
    const float* Wv = (const float*)d_in[6];
    const float* bv = (const float*)d_in[7];
    const float* Wo = (const float*)d_in[8];
    const float* bo = (const float*)d_in[9];
    float* out = (float*)d_out;

    __half *Qh, *Ql, *Kh, *Vh, *AOh, *AOl, *xh, *xl, *zh, *zl;
    float* Part;
    cudaGetSymbolAddress((void**)&Qh,  g_Qh);
    cudaGetSymbolAddress((void**)&Ql,  g_Ql);
    cudaGetSymbolAddress((void**)&Kh,  g_Kh);
    cudaGetSymbolAddress((void**)&Vh,  g_Vh);
    cudaGetSymbolAddress((void**)&AOh, g_AOh);
    cudaGetSymbolAddress((void**)&AOl, g_AOl);
    cudaGetSymbolAddress((void**)&Part, g_part);
    cudaGetSymbolAddress((void**)&xh,  g_xh);
    cudaGetSymbolAddress((void**)&xl,  g_xl);
    cudaGetSymbolAddress((void**)&zh,  g_zh);
    cudaGetSymbolAddress((void**)&zl,  g_zl);

    cudaFuncSetAttribute(gemm_mma3_kernel,
                         cudaFuncAttributeMaxDynamicSharedMemorySize, GSMEM);

    // Pre-split activations
    conv_split_kernel<<<128, 256>>>((const float4*)z, (ull*)zh, (ull*)zl, 32768);
    conv_split_kernel<<<256, 256>>>((const float4*)x, (ull*)xh, (ull*)xl, 65536);

    // QKV projections: Q -> fp16 hi/lo, K/V -> fp16 hi
    dim3 gQKV(DTOT / 256, TOK / 128, 1);
    gemm_mma3_kernel<<<gQKV, 512, GSMEM>>>(zh, zl, 256, Wq, DTOT, bq, 1,
                                           nullptr, Qh, Ql, DTOT, 0, 256);
    gemm_mma3_kernel<<<gQKV, 512, GSMEM>>>(xh, xl, 512, Wk, DTOT, bk, 2,
                                           nullptr, Kh, nullptr, DTOT, 0, 512);
    gemm_mma3_kernel<<<gQKV, 512, GSMEM>>>(xh, xl, 512, Wv, DTOT, bv, 2,
                                           nullptr, Vh, nullptr, DTOT, 0, 512);

    // Attention: 4096 heads; writes AO as fp16 hi/lo
    attn_mma_kernel<<<4096, 128>>>(Qh, Ql, Kh, Vh, AOh, AOl);

    // Output projection: split-K partials then reduce (+bias)
    dim3 gO(512 / 256, 512 / 128, NSPLIT);
    gemm_mma3_kernel<<<gO, 512, GSMEM>>>(AOh, AOl, DTOT, Wo, 512, nullptr, 0,
                                         Part, nullptr, nullptr, 512,
                                         (size_t)512 * 512, DTOT / NSPLIT);

    reduce_out_kernel<<<256, 256>>>((const float4*)Part, (const float4*)bo,
                                    (float4*)out);
}